// round 9
// baseline (speedup 1.0000x reference)
#include <cuda_runtime.h>
#include <cstdint>

#define NN 100000
#define RR 3
#define EE 800000
#define LL 200000

// bf16 stage geometry: 16 rows x 64 bf16 per tile, 144B row stride (conflict-free ldmatrix)
#define STW    144
#define TILE_B 2304
#define WSTAGE (4 * TILE_B)          // 4 tiles per warp: aggB, aggS, rootB, rootS
#define SM_TOTAL (8 * WSTAGE)        // 73728 B dynamic smem

// ---------------- scratch ----------------
__device__ __align__(16) float g_agg[(size_t)2 * RR * NN * 64];
__device__ __align__(16) float g_mix[(size_t)NN * 64];
__device__ __align__(16) float g_z[(size_t)NN * 2];
__device__ float g_score[6];   // [layer*3 + r]

// pre-split weight fragments (bf16 big/small, MMA B-fragment order), both layers
#define WF_REL  0
#define WF_ROOT 3072
#define WF_WI   6144
#define WF_WH   9216
#define WF_ATT  12288
#define WF_LAYER 13312
__device__ __align__(16) uint4 g_wfrag[2 * WF_LAYER];

// ---------------- bf16 helpers ----------------
__device__ __forceinline__ unsigned pack_bf2(float lo, float hi) {
    unsigned d;
    asm("cvt.rn.bf16x2.f32 %0, %1, %2;" : "=r"(d) : "f"(hi), "f"(lo));
    return d;
}
__device__ __forceinline__ float bf_lo(unsigned v) { return __uint_as_float(v << 16); }
__device__ __forceinline__ float bf_hi(unsigned v) { return __uint_as_float(v & 0xffff0000u); }
__device__ __forceinline__ void split2(float x, float y, unsigned& big, unsigned& small) {
    big = pack_bf2(x, y);
    small = pack_bf2(x - bf_lo(big), y - bf_hi(big));
}
__device__ __forceinline__ void mma_bf(float* d, const unsigned* a, unsigned b0, unsigned b1) {
    asm volatile(
        "mma.sync.aligned.m16n8k16.row.col.f32.bf16.bf16.f32 "
        "{%0,%1,%2,%3},{%4,%5,%6,%7},{%8,%9},{%0,%1,%2,%3};"
        : "+f"(d[0]), "+f"(d[1]), "+f"(d[2]), "+f"(d[3])
        : "r"(a[0]), "r"(a[1]), "r"(a[2]), "r"(a[3]), "r"(b0), "r"(b1));
}
// 3-term split product: (Ab+As)(Bb+Bs) ~= Ab*Bb + Ab*Bs + As*Bb
__device__ __forceinline__ void mma3(float* d, const unsigned* ab, const unsigned* as, uint4 F) {
    mma_bf(d, ab, F.x, F.y);
    mma_bf(d, ab, F.z, F.w);
    mma_bf(d, as, F.x, F.y);
}
__device__ __forceinline__ uint32_t smem_u32(const void* p) {
    uint32_t a;
    asm("{ .reg .u64 t; cvta.to.shared.u64 t, %1; cvt.u32.u64 %0, t; }" : "=r"(a) : "l"(p));
    return a;
}
// ldmatrix x4: r0..r3 == a0..a3 of m16n8k16 A fragment
__device__ __forceinline__ void ldm_x4(unsigned* r, uint32_t a) {
    asm volatile("ldmatrix.sync.aligned.m8n8.x4.shared.b16 {%0,%1,%2,%3}, [%4];"
                 : "=r"(r[0]), "=r"(r[1]), "=r"(r[2]), "=r"(r[3]) : "r"(a));
}
// per-lane submatrix row address inside a tile: rows via lane&15, +16B for k-hi half
__device__ __forceinline__ uint32_t ldm_addr(uint32_t tbase, int lane, int ks) {
    return tbase + (lane & 15) * STW + ((lane >> 4) << 4) + ks * 32;
}
// load one 16x16 A-tile fragment from row-major [*, 64] GLOBAL fp32 matrix and split
__device__ __forceinline__ void load_asplit(const float* base, int nA, int nB, int k0,
                                            unsigned* ab, unsigned* as) {
    float2 v;
    v = *(const float2*)(base + (size_t)nA * 64 + k0);      split2(v.x, v.y, ab[0], as[0]);
    v = *(const float2*)(base + (size_t)nB * 64 + k0);      split2(v.x, v.y, ab[1], as[1]);
    v = *(const float2*)(base + (size_t)nA * 64 + k0 + 8);  split2(v.x, v.y, ab[2], as[2]);
    v = *(const float2*)(base + (size_t)nB * 64 + k0 + 8);  split2(v.x, v.y, ab[3], as[3]);
}
// block-cooperative: global fp32 [128 x 64] -> per-warp bf16 big/small stage tiles
__device__ __forceinline__ void stage_tile(const float* src, int node0, char* smb,
                                           int offB, int offS, int tid) {
    for (int u = tid; u < 1024; u += 256) {
        int row = u >> 3, ch = u & 7;
        int node = min(node0 + row, NN - 1);
        int w = row >> 4, lr = row & 15;
        const float4* p = (const float4*)(src + (size_t)node * 64 + ch * 8);
        float4 v0 = p[0], v1 = p[1];
        unsigned b0, s0, b1, s1, b2, s2, b3, s3;
        split2(v0.x, v0.y, b0, s0);
        split2(v0.z, v0.w, b1, s1);
        split2(v1.x, v1.y, b2, s2);
        split2(v1.z, v1.w, b3, s3);
        int off = w * WSTAGE + lr * STW + ch * 16;
        *(uint4*)(smb + offB + off) = make_uint4(b0, b1, b2, b3);
        *(uint4*)(smb + offS + off) = make_uint4(s0, s1, s2, s3);
    }
}

// ---------------- presplit ALL weights (both layers) in one launch ----------------
__global__ void k_presplit(
    const float* __restrict__ w1rel, const float* __restrict__ w1root,
    const float* __restrict__ wi1, const float* __restrict__ wh1,
    const float* __restrict__ kw1,
    const float* __restrict__ w2rel, const float* __restrict__ w2root,
    const float* __restrict__ wi2, const float* __restrict__ wh2,
    const float* __restrict__ kw2) {
    int f = blockIdx.x * blockDim.x + threadIdx.x;
    if (f >= 2 * WF_LAYER) return;
    int l = f / WF_LAYER;
    int fo = f - l * WF_LAYER;
    const float* W;
    int fl;
    if (fo < 3072)       { W = l ? w2rel : w1rel;   fl = fo; }
    else if (fo < 6144)  { W = l ? w2root : w1root; fl = fo - 3072; }
    else if (fo < 9216)  { W = l ? wi2 : wi1;       fl = fo - 6144; }
    else if (fo < 12288) { W = l ? wh2 : wh1;       fl = fo - 9216; }
    else                 { W = l ? kw2 : kw1;       fl = fo - 12288; }
    int lane = fl & 31;
    int ks = (fl >> 5) & 3;
    int j = fl >> 7;
    int g = lane >> 2, t = lane & 3;
    const float* row = W + (size_t)(j * 8 + g) * 64;
    int k0 = ks * 16 + 2 * t;
    float w0 = row[k0], w1 = row[k0 + 1], w2 = row[k0 + 8], w3 = row[k0 + 9];
    unsigned b0, s0, b1, s1;
    split2(w0, w1, b0, s0);
    split2(w2, w3, b1, s1);
    g_wfrag[f] = make_uint4(b0, b1, s0, s1);
}

// ---------------- zero both agg halves + scores ----------------
__global__ void k_zeroall() {
    int i = blockIdx.x * blockDim.x + threadIdx.x;
    const int tot4 = 2 * RR * NN * 16;
    if (i < tot4) ((float4*)g_agg)[i] = make_float4(0.f, 0.f, 0.f, 0.f);
    if (i < 6) g_score[i] = 0.f;
}

// ---------------- scatter: agg[layer][r][dst] += feat[src], red.v4 ----------------
__global__ void k_scatter(const float* __restrict__ feat, int layer,
                          const int* __restrict__ ei) {
    unsigned idx = blockIdx.x * blockDim.x + threadIdx.x;
    if (idx >= (unsigned)RR * EE * 16u) return;
    const float* f = layer ? g_mix : feat;
    unsigned chunk = idx & 15u;
    unsigned e = idx >> 4;
    unsigned r = e / EE;
    unsigned eo = e - r * EE;
    int s = ei[(size_t)r * 2 * EE + eo];
    int d = ei[(size_t)r * 2 * EE + EE + eo];
    float4 v = *(const float4*)(f + (size_t)s * 64 + chunk * 4);
    float* o = g_agg + ((size_t)layer * RR + r) * NN * 64 + (size_t)d * 64 + chunk * 4;
    asm volatile("red.global.add.v4.f32 [%0], {%1, %2, %3, %4};"
                 :: "l"(o), "f"(v.x), "f"(v.y), "f"(v.z), "f"(v.w) : "memory");
}

// ---------------- GRU epilogue ----------------
__device__ __forceinline__ float gru_out(float gi_r, float gi_z, float gi_n,
                                         float gh_r, float gh_z, float gh_n, float p) {
    float rg = 1.f / (1.f + __expf(-(gi_r + gh_r)));
    float zg = 1.f / (1.f + __expf(-(gi_z + gh_z)));
    float ng = tanhf(gi_n + rg * gh_n);
    return (1.f - zg) * ng + zg * p;
}

// ---------------- fused layer: conv -> GRU -> attention score ----------------
__global__ __launch_bounds__(256, 2) void k_layer(
    const float* __restrict__ root_in, int layer,
    const float* __restrict__ past,
    const float* __restrict__ brel,
    const float* __restrict__ bi, const float* __restrict__ bh,
    const float* __restrict__ kb, const float* __restrict__ q,
    float* __restrict__ cur) {
    extern __shared__ char smem[];
    const uint32_t sb = smem_u32(smem);
    const int r = blockIdx.y, tid = threadIdx.x;
    const int lane = tid & 31, warp = tid >> 5;
    const int g = lane >> 2, t = lane & 3;
    const int rowA = blockIdx.x * 128 + warp * 16 + g;
    const int rowB = rowA + 8;
    const int WB = layer * WF_LAYER;
    const float* Abase = g_agg + ((size_t)layer * RR + r) * NN * 64;
    const float* Rbase = layer ? g_mix : root_in;
    const float* Pbase = past + (size_t)r * NN * 64;
    const int node0 = blockIdx.x * 128;
    const uint32_t ws = sb + warp * WSTAGE;
    // tile offsets within warp stage: 0=aggB(->H_B), 2304=aggS(->H_S), 4608=rootB(->C_B), 6912=rootS(->C_S)

    // ---- block-cooperative staging of agg + root ----
    stage_tile(Abase, node0, smem, 0, TILE_B, tid);
    stage_tile(Rbase, node0, smem, 2 * TILE_B, 3 * TILE_B, tid);
    __syncthreads();

    // ===== phase A: graphconv -> H (bf16) overwrites agg tiles =====
    {
        unsigned Ab[16], As[16], Rb[16], Rs[16];
#pragma unroll
        for (int ks = 0; ks < 4; ks++) {
            ldm_x4(Ab + ks * 4, ldm_addr(ws, lane, ks));
            ldm_x4(As + ks * 4, ldm_addr(ws + TILE_B, lane, ks));
            ldm_x4(Rb + ks * 4, ldm_addr(ws + 2 * TILE_B, lane, ks));
            ldm_x4(Rs + ks * 4, ldm_addr(ws + 3 * TILE_B, lane, ks));
        }
#pragma unroll
        for (int j = 0; j < 8; j++) {
            float acc0[4] = {}, acc1[4] = {};
#pragma unroll
            for (int ks = 0; ks < 4; ks++) {
                uint4 Fr = __ldg(g_wfrag + WB + WF_REL + ((((r * 8 + j) * 4 + ks) << 5) + lane));
                uint4 Fo = __ldg(g_wfrag + WB + WF_ROOT + ((((r * 8 + j) * 4 + ks) << 5) + lane));
                mma3(acc0, Ab + ks * 4, As + ks * 4, Fr);
                mma3(acc1, Rb + ks * 4, Rs + ks * 4, Fo);
            }
            int c0 = j * 8 + 2 * t;
            float2 bb = *(const float2*)(brel + r * 64 + c0);
            unsigned hbA, hsA, hbB, hsB;
            split2(fmaxf(acc0[0] + acc1[0] + bb.x, 0.f),
                   fmaxf(acc0[1] + acc1[1] + bb.y, 0.f), hbA, hsA);
            split2(fmaxf(acc0[2] + acc1[2] + bb.x, 0.f),
                   fmaxf(acc0[3] + acc1[3] + bb.y, 0.f), hbB, hsB);
            int offg  = g * STW + c0 * 2;
            int offg8 = (g + 8) * STW + c0 * 2;
            char* base = smem + warp * WSTAGE;
            *(unsigned*)(base + offg)           = hbA;
            *(unsigned*)(base + TILE_B + offg)  = hsA;
            *(unsigned*)(base + offg8)          = hbB;
            *(unsigned*)(base + TILE_B + offg8) = hsB;
        }
    }
    __syncwarp();

    // ===== phase B: GRU; H from stage (ldmatrix), past from global; C -> root tiles =====
    {
        const int nA = min(rowA, NN - 1), nB = min(rowB, NN - 1);
        unsigned Hb[16], Hs[16], Pb[16], Ps[16];
#pragma unroll
        for (int ks = 0; ks < 4; ks++) {
            ldm_x4(Hb + ks * 4, ldm_addr(ws, lane, ks));
            ldm_x4(Hs + ks * 4, ldm_addr(ws + TILE_B, lane, ks));
            load_asplit(Pbase, nA, nB, ks * 16 + 2 * t, Pb + ks * 4, Ps + ks * 4);
        }
#pragma unroll
        for (int j = 0; j < 8; j++) {
            float acc[6][4] = {};
#pragma unroll
            for (int ks = 0; ks < 4; ks++) {
#pragma unroll
                for (int m = 0; m < 3; m++) {
                    uint4 Fi = __ldg(g_wfrag + WB + WF_WI + ((((m * 8 + j) * 4 + ks) << 5) + lane));
                    uint4 Fh = __ldg(g_wfrag + WB + WF_WH + ((((m * 8 + j) * 4 + ks) << 5) + lane));
                    mma3(acc[m],     Hb + ks * 4, Hs + ks * 4, Fi);
                    mma3(acc[3 + m], Pb + ks * 4, Ps + ks * 4, Fh);
                }
            }
            int c0 = j * 8 + 2 * t;
            float2 bir = *(const float2*)(bi + c0);
            float2 biz = *(const float2*)(bi + 64 + c0);
            float2 bin = *(const float2*)(bi + 128 + c0);
            float2 bhr = *(const float2*)(bh + c0);
            float2 bhz = *(const float2*)(bh + 64 + c0);
            float2 bhn = *(const float2*)(bh + 128 + c0);
            float2 pA = *(const float2*)(Pbase + (size_t)nA * 64 + c0);
            float2 pB = *(const float2*)(Pbase + (size_t)nB * 64 + c0);
            float o0 = gru_out(acc[0][0] + bir.x, acc[1][0] + biz.x, acc[2][0] + bin.x,
                               acc[3][0] + bhr.x, acc[4][0] + bhz.x, acc[5][0] + bhn.x, pA.x);
            float o1 = gru_out(acc[0][1] + bir.y, acc[1][1] + biz.y, acc[2][1] + bin.y,
                               acc[3][1] + bhr.y, acc[4][1] + bhz.y, acc[5][1] + bhn.y, pA.y);
            float o2 = gru_out(acc[0][2] + bir.x, acc[1][2] + biz.x, acc[2][2] + bin.x,
                               acc[3][2] + bhr.x, acc[4][2] + bhz.x, acc[5][2] + bhn.x, pB.x);
            float o3 = gru_out(acc[0][3] + bir.y, acc[1][3] + biz.y, acc[2][3] + bin.y,
                               acc[3][3] + bhr.y, acc[4][3] + bhz.y, acc[5][3] + bhn.y, pB.y);
            if (rowA < NN) *(float2*)(cur + ((size_t)r * NN + rowA) * 64 + c0) = make_float2(o0, o1);
            if (rowB < NN) *(float2*)(cur + ((size_t)r * NN + rowB) * 64 + c0) = make_float2(o2, o3);
            unsigned cbA, csA, cbB, csB;
            split2(o0, o1, cbA, csA);
            split2(o2, o3, cbB, csB);
            int offg  = g * STW + c0 * 2;
            int offg8 = (g + 8) * STW + c0 * 2;
            char* base = smem + warp * WSTAGE + 2 * TILE_B;
            *(unsigned*)(base + offg)           = cbA;
            *(unsigned*)(base + TILE_B + offg)  = csA;
            *(unsigned*)(base + offg8)          = cbB;
            *(unsigned*)(base + TILE_B + offg8) = csB;
        }
    }
    __syncwarp();

    // ===== phase C: attention score; C from stage =====
    {
        unsigned Cb[16], Cs[16];
#pragma unroll
        for (int ks = 0; ks < 4; ks++) {
            ldm_x4(Cb + ks * 4, ldm_addr(ws + 2 * TILE_B, lane, ks));
            ldm_x4(Cs + ks * 4, ldm_addr(ws + 3 * TILE_B, lane, ks));
        }
        float ssum = 0.f;
#pragma unroll
        for (int j = 0; j < 8; j++) {
            float acc[4] = {};
#pragma unroll
            for (int ks = 0; ks < 4; ks++) {
                uint4 F = __ldg(g_wfrag + WB + WF_ATT + (((j * 4 + ks) << 5) + lane));
                mma3(acc, Cb + ks * 4, Cs + ks * 4, F);
            }
            int c0 = j * 8 + 2 * t;
            float2 kbv = *(const float2*)(kb + c0);
            float2 qv  = *(const float2*)(q + c0);
            if (rowA < NN)
                ssum += qv.x * tanhf(acc[0] + kbv.x) + qv.y * tanhf(acc[1] + kbv.y);
            if (rowB < NN)
                ssum += qv.x * tanhf(acc[2] + kbv.x) + qv.y * tanhf(acc[3] + kbv.y);
        }
#pragma unroll
        for (int o = 16; o; o >>= 1) ssum += __shfl_down_sync(0xffffffffu, ssum, o);
        if (lane == 0) atomicAdd(&g_score[layer * 3 + r], ssum);
    }
}

// ---------------- softmax helper (inline, per thread) ----------------
__device__ __forceinline__ void softmax3(int layer, float& a0, float& a1, float& a2) {
    const float inv = 1.0f / (float)NN;
    float s0 = g_score[layer * 3 + 0] * inv;
    float s1 = g_score[layer * 3 + 1] * inv;
    float s2 = g_score[layer * 3 + 2] * inv;
    float m = fmaxf(s0, fmaxf(s1, s2));
    float e0 = __expf(s0 - m), e1 = __expf(s1 - m), e2 = __expf(s2 - m);
    float d = 1.f / (e0 + e1 + e2);
    a0 = e0 * d; a1 = e1 * d; a2 = e2 * d;
}

// ---------------- attention mix (softmax fused) ----------------
__global__ void k_mix(const float* __restrict__ cur) {
    int i = blockIdx.x * blockDim.x + threadIdx.x;
    if (i >= NN * 16) return;
    float a0, a1, a2;
    softmax3(0, a0, a1, a2);
    const float4* c = (const float4*)cur;
    float4 v0 = c[i], v1 = c[i + (size_t)NN * 16], v2 = c[i + (size_t)2 * NN * 16];
    float4 o;
    o.x = a0 * v0.x + a1 * v1.x + a2 * v2.x;
    o.y = a0 * v0.y + a1 * v1.y + a2 * v2.y;
    o.z = a0 * v0.z + a1 * v1.z + a2 * v2.z;
    o.w = a0 * v0.w + a1 * v1.w + a2 * v2.w;
    ((float4*)g_mix)[i] = o;
}

// ---------------- final projection (softmax fused) ----------------
__global__ __launch_bounds__(128) void k_zfuse(
    const float* __restrict__ cur2, const float* __restrict__ postW,
    const float* __restrict__ postb) {
    int node = blockIdx.x * blockDim.x + threadIdx.x;
    if (node >= NN) return;
    float a0, a1, a2;
    softmax3(1, a0, a1, a2);
    const float4* c0 = (const float4*)(cur2 + (size_t)node * 64);
    const float4* c1 = (const float4*)(cur2 + ((size_t)NN + node) * 64);
    const float4* c2 = (const float4*)(cur2 + ((size_t)2 * NN + node) * 64);
    const float4* w0 = (const float4*)postW;
    const float4* w1 = (const float4*)(postW + 64);
    float z0 = postb[0], z1 = postb[1];
#pragma unroll
    for (int i = 0; i < 16; i++) {
        float4 u0 = c0[i], u1 = c1[i], u2 = c2[i];
        float4 m;
        m.x = a0 * u0.x + a1 * u1.x + a2 * u2.x;
        m.y = a0 * u0.y + a1 * u1.y + a2 * u2.y;
        m.z = a0 * u0.z + a1 * u1.z + a2 * u2.z;
        m.w = a0 * u0.w + a1 * u1.w + a2 * u2.w;
        float4 p0 = w0[i], p1 = w1[i];
        z0 += m.x * p0.x + m.y * p0.y + m.z * p0.z + m.w * p0.w;
        z1 += m.x * p1.x + m.y * p1.y + m.z * p1.z + m.w * p1.w;
    }
    g_z[2 * node] = z0;
    g_z[2 * node + 1] = z1;
}

// ---------------- link scores ----------------
__global__ void k_score(const int* __restrict__ eli, const float* __restrict__ rel,
                        float* __restrict__ scores) {
    int idx = blockIdx.x * blockDim.x + threadIdx.x;
    if (idx >= RR * LL) return;
    int r = idx / LL;
    int l = idx - r * LL;
    int hd = eli[(size_t)r * 2 * LL + l];
    int tl = eli[(size_t)r * 2 * LL + LL + l];
    float hr = g_z[2 * hd], hi = g_z[2 * hd + 1];
    float tr = g_z[2 * tl], ti = g_z[2 * tl + 1];
    float rr = rel[2 * r], ri = rel[2 * r + 1];
    scores[idx] = hr * rr * tr + hi * rr * ti + hr * ri * ti - hi * ri * tr;
}

// ---------------- host ----------------
extern "C" void kernel_launch(void* const* d_in, const int* in_sizes, int n_in,
                              void* d_out, int out_size) {
    const float* x      = (const float*)d_in[0];
    const int*   ei     = (const int*)d_in[1];
    const int*   eli    = (const int*)d_in[2];
    const float* past1  = (const float*)d_in[3];
    const float* past2  = (const float*)d_in[4];
    const float* W1rel  = (const float*)d_in[5];
    const float* b1rel  = (const float*)d_in[6];
    const float* W1root = (const float*)d_in[7];
    const float* g1Wi   = (const float*)d_in[8];
    const float* g1Wh   = (const float*)d_in[9];
    const float* g1bi   = (const float*)d_in[10];
    const float* g1bh   = (const float*)d_in[11];
    const float* k1W    = (const float*)d_in[12];
    const float* k1b    = (const float*)d_in[13];
    const float* q1     = (const float*)d_in[14];
    const float* W2rel  = (const float*)d_in[15];
    const float* b2rel  = (const float*)d_in[16];
    const float* W2root = (const float*)d_in[17];
    const float* g2Wi   = (const float*)d_in[18];
    const float* g2Wh   = (const float*)d_in[19];
    const float* g2bi   = (const float*)d_in[20];
    const float* g2bh   = (const float*)d_in[21];
    const float* k2W    = (const float*)d_in[22];
    const float* k2b    = (const float*)d_in[23];
    const float* q2     = (const float*)d_in[24];
    const float* postW  = (const float*)d_in[25];
    const float* postb  = (const float*)d_in[26];
    const float* relemb = (const float*)d_in[27];

    float* out    = (float*)d_out;
    float* scores = out;
    float* cur1   = out + (size_t)RR * LL;
    float* cur2   = cur1 + (size_t)RR * NN * 64;

    cudaFuncSetAttribute(k_layer, cudaFuncAttributeMaxDynamicSharedMemorySize, SM_TOTAL);

    dim3 gridL((NN + 127) / 128, RR);   // 782 x 3
    const int scat_blocks = (RR * EE * 16 + 255) / 256;

    k_zeroall<<<(2 * RR * NN * 16 + 255) / 256, 256>>>();
    k_presplit<<<(2 * WF_LAYER + 255) / 256, 256>>>(
        W1rel, W1root, g1Wi, g1Wh, k1W, W2rel, W2root, g2Wi, g2Wh, k2W);
    k_scatter<<<scat_blocks, 256>>>(x, 0, ei);
    k_layer<<<gridL, 256, SM_TOTAL>>>(x, 0, past1, b1rel, g1bi, g1bh, k1b, q1, cur1);
    k_mix<<<(NN * 16 + 255) / 256, 256>>>(cur1);
    k_scatter<<<scat_blocks, 256>>>(x, 1, ei);   // profiled launch (-s 5 -c 1)
    k_layer<<<gridL, 256, SM_TOTAL>>>(x, 1, past2, b2rel, g2bi, g2bh, k2b, q2, cur2);
    k_zfuse<<<(NN + 127) / 128, 128>>>(cur2, postW, postb);
    k_score<<<(RR * LL + 255) / 256, 256>>>(eli, relemb, scores);
}

// round 10
// speedup vs baseline: 1.2885x; 1.2885x over previous
#include <cuda_runtime.h>
#include <cstdint>

#define NN 100000
#define RR 3
#define EE 800000
#define LL 200000

// ---------------- scratch ----------------
__device__ __align__(16) float g_agg[(size_t)2 * RR * NN * 64];
__device__ __align__(16) float g_mix[(size_t)NN * 64];
__device__ __align__(16) float g_z[(size_t)NN * 2];
__device__ float g_score[6];   // [layer*3 + r]

// fp16 weight fragments (single-precision-weight 2-term scheme), MMA B-fragment order
#define WF_REL  0
#define WF_ROOT 3072
#define WF_WI   6144
#define WF_WH   9216
#define WF_ATT  12288
#define WF_LAYER 13312
__device__ __align__(16) uint2 g_wfrag[2 * WF_LAYER];

// ---------------- fp16 helpers ----------------
__device__ __forceinline__ unsigned pack_h2(float x, float y) {   // lo=x, hi=y
    unsigned d;
    asm("cvt.rn.f16x2.f32 %0, %1, %2;" : "=r"(d) : "f"(y), "f"(x));
    return d;
}
__device__ __forceinline__ void unpack_h2(unsigned v, float& x, float& y) {
    asm("{ .reg .b16 l, h; mov.b32 {l, h}, %2; cvt.f32.f16 %0, l; cvt.f32.f16 %1, h; }"
        : "=f"(x), "=f"(y) : "r"(v));
}
// split fp32 pair into fp16 big + fp16 residual
__device__ __forceinline__ void split2h(float x, float y, unsigned& big, unsigned& small) {
    big = pack_h2(x, y);
    float bx, by;
    unpack_h2(big, bx, by);
    small = pack_h2(x - bx, y - by);
}
__device__ __forceinline__ void mma_h(float* d, const unsigned* a, unsigned b0, unsigned b1) {
    asm volatile(
        "mma.sync.aligned.m16n8k16.row.col.f32.f16.f16.f32 "
        "{%0,%1,%2,%3},{%4,%5,%6,%7},{%8,%9},{%0,%1,%2,%3};"
        : "+f"(d[0]), "+f"(d[1]), "+f"(d[2]), "+f"(d[3])
        : "r"(a[0]), "r"(a[1]), "r"(a[2]), "r"(a[3]), "r"(b0), "r"(b1));
}
// 2-term: (Ah+Al)*Bh
__device__ __forceinline__ void mma2(float* d, const unsigned* ah, const unsigned* al, uint2 F) {
    mma_h(d, ah, F.x, F.y);
    mma_h(d, al, F.x, F.y);
}
// load one 16x16 A-tile fragment from row-major [*, 64] global fp32 matrix, split to fp16
__device__ __forceinline__ void load_asplit(const float* base, int nA, int nB, int k0,
                                            unsigned* ah, unsigned* al) {
    float2 v;
    v = *(const float2*)(base + (size_t)nA * 64 + k0);      split2h(v.x, v.y, ah[0], al[0]);
    v = *(const float2*)(base + (size_t)nB * 64 + k0);      split2h(v.x, v.y, ah[1], al[1]);
    v = *(const float2*)(base + (size_t)nA * 64 + k0 + 8);  split2h(v.x, v.y, ah[2], al[2]);
    v = *(const float2*)(base + (size_t)nB * 64 + k0 + 8);  split2h(v.x, v.y, ah[3], al[3]);
}

// stage geometry: per warp 2 tiles (hi, lo), each 16 rows x 32 words, row stride 36 words
#define STROW 36
#define TILE_W 576
#define WST 1152   // words per warp

// ---------------- presplit ALL weights (both layers) to fp16 fragments ----------------
__global__ void k_presplit(
    const float* __restrict__ w1rel, const float* __restrict__ w1root,
    const float* __restrict__ wi1, const float* __restrict__ wh1,
    const float* __restrict__ kw1,
    const float* __restrict__ w2rel, const float* __restrict__ w2root,
    const float* __restrict__ wi2, const float* __restrict__ wh2,
    const float* __restrict__ kw2) {
    int f = blockIdx.x * blockDim.x + threadIdx.x;
    if (f >= 2 * WF_LAYER) return;
    int l = f / WF_LAYER;
    int fo = f - l * WF_LAYER;
    const float* W;
    int fl;
    if (fo < 3072)       { W = l ? w2rel : w1rel;   fl = fo; }
    else if (fo < 6144)  { W = l ? w2root : w1root; fl = fo - 3072; }
    else if (fo < 9216)  { W = l ? wi2 : wi1;       fl = fo - 6144; }
    else if (fo < 12288) { W = l ? wh2 : wh1;       fl = fo - 9216; }
    else                 { W = l ? kw2 : kw1;       fl = fo - 12288; }
    int lane = fl & 31;
    int ks = (fl >> 5) & 3;
    int j = fl >> 7;
    int g = lane >> 2, t = lane & 3;
    const float* row = W + (size_t)(j * 8 + g) * 64;
    int k0 = ks * 16 + 2 * t;
    unsigned b0 = pack_h2(row[k0], row[k0 + 1]);
    unsigned b1 = pack_h2(row[k0 + 8], row[k0 + 9]);
    g_wfrag[f] = make_uint2(b0, b1);
}

// ---------------- zero both agg halves + scores ----------------
__global__ void k_zeroall() {
    int i = blockIdx.x * blockDim.x + threadIdx.x;
    const int tot4 = 2 * RR * NN * 16;
    if (i < tot4) ((float4*)g_agg)[i] = make_float4(0.f, 0.f, 0.f, 0.f);
    if (i < 6) g_score[i] = 0.f;
}

// ---------------- scatter: agg[layer][r][dst] += feat[src], red.v4 ----------------
__global__ void k_scatter(const float* __restrict__ feat, int layer,
                          const int* __restrict__ ei) {
    unsigned idx = blockIdx.x * blockDim.x + threadIdx.x;
    if (idx >= (unsigned)RR * EE * 16u) return;
    const float* f = layer ? g_mix : feat;
    unsigned chunk = idx & 15u;
    unsigned e = idx >> 4;
    unsigned r = e / EE;
    unsigned eo = e - r * EE;
    int s = ei[(size_t)r * 2 * EE + eo];
    int d = ei[(size_t)r * 2 * EE + EE + eo];
    float4 v = *(const float4*)(f + (size_t)s * 64 + chunk * 4);
    float* o = g_agg + ((size_t)layer * RR + r) * NN * 64 + (size_t)d * 64 + chunk * 4;
    asm volatile("red.global.add.v4.f32 [%0], {%1, %2, %3, %4};"
                 :: "l"(o), "f"(v.x), "f"(v.y), "f"(v.z), "f"(v.w) : "memory");
}

// ---------------- GRU epilogue ----------------
__device__ __forceinline__ float gru_out(float gi_r, float gi_z, float gi_n,
                                         float gh_r, float gh_z, float gh_n, float p) {
    float rg = 1.f / (1.f + __expf(-(gi_r + gh_r)));
    float zg = 1.f / (1.f + __expf(-(gi_z + gh_z)));
    float ng = tanhf(gi_n + rg * gh_n);
    return (1.f - zg) * ng + zg * p;
}

// ---------------- fused layer: conv -> GRU -> attention score ----------------
__global__ __launch_bounds__(256, 2) void k_layer(
    const float* __restrict__ root_in, int layer,
    const float* __restrict__ past,
    const float* __restrict__ brel,
    const float* __restrict__ bi, const float* __restrict__ bh,
    const float* __restrict__ kb, const float* __restrict__ q,
    float* __restrict__ cur) {
    __shared__ unsigned sStage[8 * WST];   // 36864 B: per-warp packed f16x2 hi/lo tiles
    const int r = blockIdx.y, tid = threadIdx.x;
    const int lane = tid & 31, warp = tid >> 5;
    const int g = lane >> 2, t = lane & 3;
    const int rowA = blockIdx.x * 128 + warp * 16 + g;
    const int rowB = rowA + 8;
    const int nA = min(rowA, NN - 1), nB = min(rowB, NN - 1);
    const int WB = layer * WF_LAYER;
    const float* Abase = g_agg + ((size_t)layer * RR + r) * NN * 64;
    const float* Rbase = layer ? g_mix : root_in;
    const float* Pbase = past + (size_t)r * NN * 64;
    const int node0 = blockIdx.x * 128;
    unsigned* st = sStage + warp * WST;   // [0:576) hi tile, [576:1152) lo tile

    // ===== phase A: graphconv -> H (fp16 split) into stage =====
    {
        unsigned Ah[16], Al[16], Rh[16], Rl[16];
#pragma unroll
        for (int ks = 0; ks < 4; ks++) {
            int k0 = ks * 16 + 2 * t;
            load_asplit(Abase, nA, nB, k0, Ah + ks * 4, Al + ks * 4);
            load_asplit(Rbase, nA, nB, k0, Rh + ks * 4, Rl + ks * 4);
        }
#pragma unroll
        for (int j = 0; j < 8; j++) {
            float acc0[4] = {}, acc1[4] = {};
#pragma unroll
            for (int ks = 0; ks < 4; ks++) {
                uint2 Fr = __ldg(g_wfrag + WB + WF_REL + ((((r * 8 + j) * 4 + ks) << 5) + lane));
                uint2 Fo = __ldg(g_wfrag + WB + WF_ROOT + ((((r * 8 + j) * 4 + ks) << 5) + lane));
                mma2(acc0, Ah + ks * 4, Al + ks * 4, Fr);
                mma2(acc1, Rh + ks * 4, Rl + ks * 4, Fo);
            }
            int c0 = j * 8 + 2 * t;
            float2 bb = *(const float2*)(brel + r * 64 + c0);
            unsigned hhA, hlA, hhB, hlB;
            split2h(fmaxf(acc0[0] + acc1[0] + bb.x, 0.f),
                    fmaxf(acc0[1] + acc1[1] + bb.y, 0.f), hhA, hlA);
            split2h(fmaxf(acc0[2] + acc1[2] + bb.x, 0.f),
                    fmaxf(acc0[3] + acc1[3] + bb.y, 0.f), hhB, hlB);
            int wj = j * 4 + t;
            st[g * STROW + wj] = hhA;
            st[(g + 8) * STROW + wj] = hhB;
            st[TILE_W + g * STROW + wj] = hlA;
            st[TILE_W + (g + 8) * STROW + wj] = hlB;
        }
    }
    __syncwarp();

    // ===== phase B: GRU; H from stage, past from global; C -> stage =====
    {
        unsigned Hh[16], Hl[16], Ph[16], Pl[16];
#pragma unroll
        for (int ks = 0; ks < 4; ks++) {
            int w0 = ks * 8 + t;
            Hh[ks * 4 + 0] = st[g * STROW + w0];
            Hh[ks * 4 + 1] = st[(g + 8) * STROW + w0];
            Hh[ks * 4 + 2] = st[g * STROW + w0 + 4];
            Hh[ks * 4 + 3] = st[(g + 8) * STROW + w0 + 4];
            Hl[ks * 4 + 0] = st[TILE_W + g * STROW + w0];
            Hl[ks * 4 + 1] = st[TILE_W + (g + 8) * STROW + w0];
            Hl[ks * 4 + 2] = st[TILE_W + g * STROW + w0 + 4];
            Hl[ks * 4 + 3] = st[TILE_W + (g + 8) * STROW + w0 + 4];
            load_asplit(Pbase, nA, nB, ks * 16 + 2 * t, Ph + ks * 4, Pl + ks * 4);
        }
        __syncwarp();
#pragma unroll
        for (int j = 0; j < 8; j++) {
            float acc[6][4] = {};
#pragma unroll
            for (int ks = 0; ks < 4; ks++) {
#pragma unroll
                for (int m = 0; m < 3; m++) {
                    uint2 Fi = __ldg(g_wfrag + WB + WF_WI + ((((m * 8 + j) * 4 + ks) << 5) + lane));
                    uint2 Fh = __ldg(g_wfrag + WB + WF_WH + ((((m * 8 + j) * 4 + ks) << 5) + lane));
                    mma2(acc[m],     Hh + ks * 4, Hl + ks * 4, Fi);
                    mma2(acc[3 + m], Ph + ks * 4, Pl + ks * 4, Fh);
                }
            }
            int c0 = j * 8 + 2 * t;
            float2 bir = *(const float2*)(bi + c0);
            float2 biz = *(const float2*)(bi + 64 + c0);
            float2 bin = *(const float2*)(bi + 128 + c0);
            float2 bhr = *(const float2*)(bh + c0);
            float2 bhz = *(const float2*)(bh + 64 + c0);
            float2 bhn = *(const float2*)(bh + 128 + c0);
            float2 pA = *(const float2*)(Pbase + (size_t)nA * 64 + c0);
            float2 pB = *(const float2*)(Pbase + (size_t)nB * 64 + c0);
            float o0 = gru_out(acc[0][0] + bir.x, acc[1][0] + biz.x, acc[2][0] + bin.x,
                               acc[3][0] + bhr.x, acc[4][0] + bhz.x, acc[5][0] + bhn.x, pA.x);
            float o1 = gru_out(acc[0][1] + bir.y, acc[1][1] + biz.y, acc[2][1] + bin.y,
                               acc[3][1] + bhr.y, acc[4][1] + bhz.y, acc[5][1] + bhn.y, pA.y);
            float o2 = gru_out(acc[0][2] + bir.x, acc[1][2] + biz.x, acc[2][2] + bin.x,
                               acc[3][2] + bhr.x, acc[4][2] + bhz.x, acc[5][2] + bhn.x, pB.x);
            float o3 = gru_out(acc[0][3] + bir.y, acc[1][3] + biz.y, acc[2][3] + bin.y,
                               acc[3][3] + bhr.y, acc[4][3] + bhz.y, acc[5][3] + bhn.y, pB.y);
            if (rowA < NN) *(float2*)(cur + ((size_t)r * NN + rowA) * 64 + c0) = make_float2(o0, o1);
            if (rowB < NN) *(float2*)(cur + ((size_t)r * NN + rowB) * 64 + c0) = make_float2(o2, o3);
            unsigned chA, clA, chB, clB;
            split2h(o0, o1, chA, clA);
            split2h(o2, o3, chB, clB);
            int wj = j * 4 + t;
            st[g * STROW + wj] = chA;
            st[(g + 8) * STROW + wj] = chB;
            st[TILE_W + g * STROW + wj] = clA;
            st[TILE_W + (g + 8) * STROW + wj] = clB;
        }
    }
    __syncwarp();

    // ===== phase C: attention score; C from stage (2-way accumulator ILP) =====
    {
        unsigned Ch[16], Cl[16];
#pragma unroll
        for (int ks = 0; ks < 4; ks++) {
            int w0 = ks * 8 + t;
            Ch[ks * 4 + 0] = st[g * STROW + w0];
            Ch[ks * 4 + 1] = st[(g + 8) * STROW + w0];
            Ch[ks * 4 + 2] = st[g * STROW + w0 + 4];
            Ch[ks * 4 + 3] = st[(g + 8) * STROW + w0 + 4];
            Cl[ks * 4 + 0] = st[TILE_W + g * STROW + w0];
            Cl[ks * 4 + 1] = st[TILE_W + (g + 8) * STROW + w0];
            Cl[ks * 4 + 2] = st[TILE_W + g * STROW + w0 + 4];
            Cl[ks * 4 + 3] = st[TILE_W + (g + 8) * STROW + w0 + 4];
        }
        float ssum = 0.f;
#pragma unroll
        for (int j = 0; j < 8; j++) {
            float accA[4] = {}, accB[4] = {};
#pragma unroll
            for (int ks = 0; ks < 4; ks++) {
                uint2 F = __ldg(g_wfrag + WB + WF_ATT + (((j * 4 + ks) << 5) + lane));
                mma2((ks & 1) ? accB : accA, Ch + ks * 4, Cl + ks * 4, F);
            }
            int c0 = j * 8 + 2 * t;
            float2 kbv = *(const float2*)(kb + c0);
            float2 qv  = *(const float2*)(q + c0);
            if (rowA < NN)
                ssum += qv.x * tanhf(accA[0] + accB[0] + kbv.x)
                      + qv.y * tanhf(accA[1] + accB[1] + kbv.y);
            if (rowB < NN)
                ssum += qv.x * tanhf(accA[2] + accB[2] + kbv.x)
                      + qv.y * tanhf(accA[3] + accB[3] + kbv.y);
        }
#pragma unroll
        for (int o = 16; o; o >>= 1) ssum += __shfl_down_sync(0xffffffffu, ssum, o);
        if (lane == 0) atomicAdd(&g_score[layer * 3 + r], ssum);
    }
}

// ---------------- softmax helper (inline, per thread) ----------------
__device__ __forceinline__ void softmax3(int layer, float& a0, float& a1, float& a2) {
    const float inv = 1.0f / (float)NN;
    float s0 = g_score[layer * 3 + 0] * inv;
    float s1 = g_score[layer * 3 + 1] * inv;
    float s2 = g_score[layer * 3 + 2] * inv;
    float m = fmaxf(s0, fmaxf(s1, s2));
    float e0 = __expf(s0 - m), e1 = __expf(s1 - m), e2 = __expf(s2 - m);
    float d = 1.f / (e0 + e1 + e2);
    a0 = e0 * d; a1 = e1 * d; a2 = e2 * d;
}

// ---------------- attention mix (softmax fused) ----------------
__global__ void k_mix(const float* __restrict__ cur) {
    int i = blockIdx.x * blockDim.x + threadIdx.x;
    if (i >= NN * 16) return;
    float a0, a1, a2;
    softmax3(0, a0, a1, a2);
    const float4* c = (const float4*)cur;
    float4 v0 = c[i], v1 = c[i + (size_t)NN * 16], v2 = c[i + (size_t)2 * NN * 16];
    float4 o;
    o.x = a0 * v0.x + a1 * v1.x + a2 * v2.x;
    o.y = a0 * v0.y + a1 * v1.y + a2 * v2.y;
    o.z = a0 * v0.z + a1 * v1.z + a2 * v2.z;
    o.w = a0 * v0.w + a1 * v1.w + a2 * v2.w;
    ((float4*)g_mix)[i] = o;
}

// ---------------- final projection (softmax fused) ----------------
__global__ __launch_bounds__(128) void k_zfuse(
    const float* __restrict__ cur2, const float* __restrict__ postW,
    const float* __restrict__ postb) {
    int node = blockIdx.x * blockDim.x + threadIdx.x;
    if (node >= NN) return;
    float a0, a1, a2;
    softmax3(1, a0, a1, a2);
    const float4* c0 = (const float4*)(cur2 + (size_t)node * 64);
    const float4* c1 = (const float4*)(cur2 + ((size_t)NN + node) * 64);
    const float4* c2 = (const float4*)(cur2 + ((size_t)2 * NN + node) * 64);
    const float4* w0 = (const float4*)postW;
    const float4* w1 = (const float4*)(postW + 64);
    float z0 = postb[0], z1 = postb[1];
#pragma unroll
    for (int i = 0; i < 16; i++) {
        float4 u0 = c0[i], u1 = c1[i], u2 = c2[i];
        float4 m;
        m.x = a0 * u0.x + a1 * u1.x + a2 * u2.x;
        m.y = a0 * u0.y + a1 * u1.y + a2 * u2.y;
        m.z = a0 * u0.z + a1 * u1.z + a2 * u2.z;
        m.w = a0 * u0.w + a1 * u1.w + a2 * u2.w;
        float4 p0 = w0[i], p1 = w1[i];
        z0 += m.x * p0.x + m.y * p0.y + m.z * p0.z + m.w * p0.w;
        z1 += m.x * p1.x + m.y * p1.y + m.z * p1.z + m.w * p1.w;
    }
    g_z[2 * node] = z0;
    g_z[2 * node + 1] = z1;
}

// ---------------- link scores ----------------
__global__ void k_score(const int* __restrict__ eli, const float* __restrict__ rel,
                        float* __restrict__ scores) {
    int idx = blockIdx.x * blockDim.x + threadIdx.x;
    if (idx >= RR * LL) return;
    int r = idx / LL;
    int l = idx - r * LL;
    int hd = eli[(size_t)r * 2 * LL + l];
    int tl = eli[(size_t)r * 2 * LL + LL + l];
    float hr = g_z[2 * hd], hi = g_z[2 * hd + 1];
    float tr = g_z[2 * tl], ti = g_z[2 * tl + 1];
    float rr = rel[2 * r], ri = rel[2 * r + 1];
    scores[idx] = hr * rr * tr + hi * rr * ti + hr * ri * ti - hi * ri * tr;
}

// ---------------- host ----------------
extern "C" void kernel_launch(void* const* d_in, const int* in_sizes, int n_in,
                              void* d_out, int out_size) {
    const float* x      = (const float*)d_in[0];
    const int*   ei     = (const int*)d_in[1];
    const int*   eli    = (const int*)d_in[2];
    const float* past1  = (const float*)d_in[3];
    const float* past2  = (const float*)d_in[4];
    const float* W1rel  = (const float*)d_in[5];
    const float* b1rel  = (const float*)d_in[6];
    const float* W1root = (const float*)d_in[7];
    const float* g1Wi   = (const float*)d_in[8];
    const float* g1Wh   = (const float*)d_in[9];
    const float* g1bi   = (const float*)d_in[10];
    const float* g1bh   = (const float*)d_in[11];
    const float* k1W    = (const float*)d_in[12];
    const float* k1b    = (const float*)d_in[13];
    const float* q1     = (const float*)d_in[14];
    const float* W2rel  = (const float*)d_in[15];
    const float* b2rel  = (const float*)d_in[16];
    const float* W2root = (const float*)d_in[17];
    const float* g2Wi   = (const float*)d_in[18];
    const float* g2Wh   = (const float*)d_in[19];
    const float* g2bi   = (const float*)d_in[20];
    const float* g2bh   = (const float*)d_in[21];
    const float* k2W    = (const float*)d_in[22];
    const float* k2b    = (const float*)d_in[23];
    const float* q2     = (const float*)d_in[24];
    const float* postW  = (const float*)d_in[25];
    const float* postb  = (const float*)d_in[26];
    const float* relemb = (const float*)d_in[27];

    float* out    = (float*)d_out;
    float* scores = out;
    float* cur1   = out + (size_t)RR * LL;
    float* cur2   = cur1 + (size_t)RR * NN * 64;

    dim3 gridL((NN + 127) / 128, RR);   // 782 x 3
    const int scat_blocks = (RR * EE * 16 + 255) / 256;

    k_zeroall<<<(2 * RR * NN * 16 + 255) / 256, 256>>>();
    k_presplit<<<(2 * WF_LAYER + 255) / 256, 256>>>(
        W1rel, W1root, g1Wi, g1Wh, k1W, W2rel, W2root, g2Wi, g2Wh, k2W);
    k_scatter<<<scat_blocks, 256>>>(x, 0, ei);
    k_layer<<<gridL, 256>>>(x, 0, past1, b1rel, g1bi, g1bh, k1b, q1, cur1);
    k_mix<<<(NN * 16 + 255) / 256, 256>>>(cur1);
    k_scatter<<<scat_blocks, 256>>>(x, 1, ei);   // profiled launch (-s 5 -c 1)
    k_layer<<<gridL, 256>>>(x, 1, past2, b2rel, g2bi, g2bh, k2b, q2, cur2);
    k_zfuse<<<(NN + 127) / 128, 128>>>(cur2, postW, postb);
    k_score<<<(RR * LL + 255) / 256, 256>>>(eli, relemb, scores);
}

// round 11
// speedup vs baseline: 1.5595x; 1.2104x over previous
#include <cuda_runtime.h>
#include <cstdint>

#define NN 100000
#define RR 3
#define EE 800000
#define LL 200000

// ---------------- scratch ----------------
// fp16 segment-sum buffers: 32 f16x2 words per node row
__device__ __align__(16) unsigned g_agg_h[(size_t)2 * RR * NN * 32];
__device__ __align__(16) unsigned g_xh[(size_t)NN * 32];    // x in fp16
__device__ __align__(16) unsigned g_mixh[(size_t)NN * 32];  // mix in fp16
__device__ __align__(16) float g_mix[(size_t)NN * 64];      // mix in fp32 (root operand)
__device__ __align__(16) float g_z[(size_t)NN * 2];
__device__ float g_score[6];   // [layer*3 + r]

// fp16 weight fragments (single-precision-weight 2-term scheme), MMA B-fragment order
#define WF_REL  0
#define WF_ROOT 3072
#define WF_WI   6144
#define WF_WH   9216
#define WF_ATT  12288
#define WF_LAYER 13312
__device__ __align__(16) uint2 g_wfrag[2 * WF_LAYER];

// ---------------- fp16 helpers ----------------
__device__ __forceinline__ unsigned pack_h2(float x, float y) {   // lo=x, hi=y
    unsigned d;
    asm("cvt.rn.f16x2.f32 %0, %1, %2;" : "=r"(d) : "f"(y), "f"(x));
    return d;
}
__device__ __forceinline__ void unpack_h2(unsigned v, float& x, float& y) {
    asm("{ .reg .b16 l, h; mov.b32 {l, h}, %2; cvt.f32.f16 %0, l; cvt.f32.f16 %1, h; }"
        : "=f"(x), "=f"(y) : "r"(v));
}
// split fp32 pair into fp16 big + fp16 residual
__device__ __forceinline__ void split2h(float x, float y, unsigned& big, unsigned& small) {
    big = pack_h2(x, y);
    float bx, by;
    unpack_h2(big, bx, by);
    small = pack_h2(x - bx, y - by);
}
__device__ __forceinline__ void mma_h(float* d, const unsigned* a, unsigned b0, unsigned b1) {
    asm volatile(
        "mma.sync.aligned.m16n8k16.row.col.f32.f16.f16.f32 "
        "{%0,%1,%2,%3},{%4,%5,%6,%7},{%8,%9},{%0,%1,%2,%3};"
        : "+f"(d[0]), "+f"(d[1]), "+f"(d[2]), "+f"(d[3])
        : "r"(a[0]), "r"(a[1]), "r"(a[2]), "r"(a[3]), "r"(b0), "r"(b1));
}
// 2-term: (Ah+Al)*Bh
__device__ __forceinline__ void mma2(float* d, const unsigned* ah, const unsigned* al, uint2 F) {
    mma_h(d, ah, F.x, F.y);
    mma_h(d, al, F.x, F.y);
}
// load one 16x16 A-tile fragment from row-major [*, 64] global fp32 matrix, split to fp16
__device__ __forceinline__ void load_asplit(const float* base, int nA, int nB, int k0,
                                            unsigned* ah, unsigned* al) {
    float2 v;
    v = *(const float2*)(base + (size_t)nA * 64 + k0);      split2h(v.x, v.y, ah[0], al[0]);
    v = *(const float2*)(base + (size_t)nB * 64 + k0);      split2h(v.x, v.y, ah[1], al[1]);
    v = *(const float2*)(base + (size_t)nA * 64 + k0 + 8);  split2h(v.x, v.y, ah[2], al[2]);
    v = *(const float2*)(base + (size_t)nB * 64 + k0 + 8);  split2h(v.x, v.y, ah[3], al[3]);
}

// stage geometry: per warp 2 tiles (hi, lo), each 16 rows x 32 words, row stride 36 words
#define STROW 36
#define TILE_W 576
#define WST 1152   // words per warp

// ---------------- presplit ALL weights (both layers) to fp16 fragments ----------------
__global__ void k_presplit(
    const float* __restrict__ w1rel, const float* __restrict__ w1root,
    const float* __restrict__ wi1, const float* __restrict__ wh1,
    const float* __restrict__ kw1,
    const float* __restrict__ w2rel, const float* __restrict__ w2root,
    const float* __restrict__ wi2, const float* __restrict__ wh2,
    const float* __restrict__ kw2) {
    int f = blockIdx.x * blockDim.x + threadIdx.x;
    if (f >= 2 * WF_LAYER) return;
    int l = f / WF_LAYER;
    int fo = f - l * WF_LAYER;
    const float* W;
    int fl;
    if (fo < 3072)       { W = l ? w2rel : w1rel;   fl = fo; }
    else if (fo < 6144)  { W = l ? w2root : w1root; fl = fo - 3072; }
    else if (fo < 9216)  { W = l ? wi2 : wi1;       fl = fo - 6144; }
    else if (fo < 12288) { W = l ? wh2 : wh1;       fl = fo - 9216; }
    else                 { W = l ? kw2 : kw1;       fl = fo - 12288; }
    int lane = fl & 31;
    int ks = (fl >> 5) & 3;
    int j = fl >> 7;
    int g = lane >> 2, t = lane & 3;
    const float* row = W + (size_t)(j * 8 + g) * 64;
    int k0 = ks * 16 + 2 * t;
    unsigned b0 = pack_h2(row[k0], row[k0 + 1]);
    unsigned b1 = pack_h2(row[k0 + 8], row[k0 + 9]);
    g_wfrag[f] = make_uint2(b0, b1);
}

// ---------------- zero agg (fp16) + convert x -> fp16 + zero scores ----------------
__global__ void k_zeroall(const float* __restrict__ x) {
    int i = blockIdx.x * blockDim.x + threadIdx.x;
    const int totz = 2 * RR * NN * 8;   // uint4 count of g_agg_h
    if (i < totz) ((uint4*)g_agg_h)[i] = make_uint4(0u, 0u, 0u, 0u);
    if (i < NN * 8) {
        const float4* p = (const float4*)(x + (size_t)i * 8);
        float4 v0 = p[0], v1 = p[1];
        ((uint4*)g_xh)[i] = make_uint4(pack_h2(v0.x, v0.y), pack_h2(v0.z, v0.w),
                                       pack_h2(v1.x, v1.y), pack_h2(v1.z, v1.w));
    }
    if (i < 6) g_score[i] = 0.f;
}

// ---------------- scatter: agg[layer][r][dst] += feat16[src], red.v4.f16x2 ----------------
__global__ void k_scatter(int layer, const int* __restrict__ ei) {
    unsigned idx = blockIdx.x * blockDim.x + threadIdx.x;
    if (idx >= (unsigned)RR * EE * 8u) return;
    const unsigned* src = layer ? g_mixh : g_xh;
    unsigned chunk = idx & 7u;
    unsigned e = idx >> 3;
    unsigned r = e / EE;
    unsigned eo = e - r * EE;
    int s = ei[(size_t)r * 2 * EE + eo];
    int d = ei[(size_t)r * 2 * EE + EE + eo];
    uint4 v = *(const uint4*)(src + (size_t)s * 32 + chunk * 4);
    unsigned* o = g_agg_h + ((size_t)((size_t)layer * RR + r) * NN + d) * 32 + chunk * 4;
    asm volatile("red.global.add.noftz.v4.f16x2 [%0], {%1, %2, %3, %4};"
                 :: "l"(o), "r"(v.x), "r"(v.y), "r"(v.z), "r"(v.w) : "memory");
}

// ---------------- GRU epilogue ----------------
__device__ __forceinline__ float gru_out(float gi_r, float gi_z, float gi_n,
                                         float gh_r, float gh_z, float gh_n, float p) {
    float rg = 1.f / (1.f + __expf(-(gi_r + gh_r)));
    float zg = 1.f / (1.f + __expf(-(gi_z + gh_z)));
    float ng = tanhf(gi_n + rg * gh_n);
    return (1.f - zg) * ng + zg * p;
}

// ---------------- fused layer: conv -> GRU -> attention score ----------------
__global__ __launch_bounds__(256, 2) void k_layer(
    const float* __restrict__ root_in, int layer,
    const float* __restrict__ past,
    const float* __restrict__ brel,
    const float* __restrict__ bi, const float* __restrict__ bh,
    const float* __restrict__ kb, const float* __restrict__ q,
    float* __restrict__ cur) {
    __shared__ unsigned sStage[8 * WST];   // per-warp packed f16x2 hi/lo tiles
    const int r = blockIdx.y, tid = threadIdx.x;
    const int lane = tid & 31, warp = tid >> 5;
    const int g = lane >> 2, t = lane & 3;
    const int rowA = blockIdx.x * 128 + warp * 16 + g;
    const int rowB = rowA + 8;
    const int nA = min(rowA, NN - 1), nB = min(rowB, NN - 1);
    const int WB = layer * WF_LAYER;
    const unsigned* Ab16 = g_agg_h + (size_t)((size_t)layer * RR + r) * NN * 32;
    const float* Rbase = layer ? g_mix : root_in;
    const float* Pbase = past + (size_t)r * NN * 64;
    unsigned* st = sStage + warp * WST;   // [0:576) hi tile, [576:1152) lo tile

    // ===== phase A: graphconv -> H (fp16 split) into stage =====
    {
        unsigned Ah[16], Rh[16], Rl[16];
#pragma unroll
        for (int ks = 0; ks < 4; ks++) {
            int w0 = ks * 8 + t;
            Ah[ks * 4 + 0] = Ab16[(size_t)nA * 32 + w0];
            Ah[ks * 4 + 1] = Ab16[(size_t)nB * 32 + w0];
            Ah[ks * 4 + 2] = Ab16[(size_t)nA * 32 + w0 + 4];
            Ah[ks * 4 + 3] = Ab16[(size_t)nB * 32 + w0 + 4];
            load_asplit(Rbase, nA, nB, ks * 16 + 2 * t, Rh + ks * 4, Rl + ks * 4);
        }
#pragma unroll
        for (int j = 0; j < 8; j++) {
            float acc0[4] = {}, acc1[4] = {};
#pragma unroll
            for (int ks = 0; ks < 4; ks++) {
                uint2 Fr = __ldg(g_wfrag + WB + WF_REL + ((((r * 8 + j) * 4 + ks) << 5) + lane));
                uint2 Fo = __ldg(g_wfrag + WB + WF_ROOT + ((((r * 8 + j) * 4 + ks) << 5) + lane));
                mma_h(acc0, Ah + ks * 4, Fr.x, Fr.y);          // agg side: exact fp16, 1 term
                mma2(acc1, Rh + ks * 4, Rl + ks * 4, Fo);      // root side: 2 terms
            }
            int c0 = j * 8 + 2 * t;
            float2 bb = *(const float2*)(brel + r * 64 + c0);
            unsigned hhA, hlA, hhB, hlB;
            split2h(fmaxf(acc0[0] + acc1[0] + bb.x, 0.f),
                    fmaxf(acc0[1] + acc1[1] + bb.y, 0.f), hhA, hlA);
            split2h(fmaxf(acc0[2] + acc1[2] + bb.x, 0.f),
                    fmaxf(acc0[3] + acc1[3] + bb.y, 0.f), hhB, hlB);
            int wj = j * 4 + t;
            st[g * STROW + wj] = hhA;
            st[(g + 8) * STROW + wj] = hhB;
            st[TILE_W + g * STROW + wj] = hlA;
            st[TILE_W + (g + 8) * STROW + wj] = hlB;
        }
    }
    __syncwarp();

    // ===== phase B: GRU; H from stage, past from global; C -> stage =====
    {
        unsigned Hh[16], Hl[16], Ph[16], Pl[16];
#pragma unroll
        for (int ks = 0; ks < 4; ks++) {
            int w0 = ks * 8 + t;
            Hh[ks * 4 + 0] = st[g * STROW + w0];
            Hh[ks * 4 + 1] = st[(g + 8) * STROW + w0];
            Hh[ks * 4 + 2] = st[g * STROW + w0 + 4];
            Hh[ks * 4 + 3] = st[(g + 8) * STROW + w0 + 4];
            Hl[ks * 4 + 0] = st[TILE_W + g * STROW + w0];
            Hl[ks * 4 + 1] = st[TILE_W + (g + 8) * STROW + w0];
            Hl[ks * 4 + 2] = st[TILE_W + g * STROW + w0 + 4];
            Hl[ks * 4 + 3] = st[TILE_W + (g + 8) * STROW + w0 + 4];
            load_asplit(Pbase, nA, nB, ks * 16 + 2 * t, Ph + ks * 4, Pl + ks * 4);
        }
        __syncwarp();
#pragma unroll
        for (int j = 0; j < 8; j++) {
            float acc[6][4] = {};
#pragma unroll
            for (int ks = 0; ks < 4; ks++) {
#pragma unroll
                for (int m = 0; m < 3; m++) {
                    uint2 Fi = __ldg(g_wfrag + WB + WF_WI + ((((m * 8 + j) * 4 + ks) << 5) + lane));
                    uint2 Fh = __ldg(g_wfrag + WB + WF_WH + ((((m * 8 + j) * 4 + ks) << 5) + lane));
                    mma2(acc[m],     Hh + ks * 4, Hl + ks * 4, Fi);
                    mma2(acc[3 + m], Ph + ks * 4, Pl + ks * 4, Fh);
                }
            }
            int c0 = j * 8 + 2 * t;
            float2 bir = *(const float2*)(bi + c0);
            float2 biz = *(const float2*)(bi + 64 + c0);
            float2 bin = *(const float2*)(bi + 128 + c0);
            float2 bhr = *(const float2*)(bh + c0);
            float2 bhz = *(const float2*)(bh + 64 + c0);
            float2 bhn = *(const float2*)(bh + 128 + c0);
            float2 pA = *(const float2*)(Pbase + (size_t)nA * 64 + c0);
            float2 pB = *(const float2*)(Pbase + (size_t)nB * 64 + c0);
            float o0 = gru_out(acc[0][0] + bir.x, acc[1][0] + biz.x, acc[2][0] + bin.x,
                               acc[3][0] + bhr.x, acc[4][0] + bhz.x, acc[5][0] + bhn.x, pA.x);
            float o1 = gru_out(acc[0][1] + bir.y, acc[1][1] + biz.y, acc[2][1] + bin.y,
                               acc[3][1] + bhr.y, acc[4][1] + bhz.y, acc[5][1] + bhn.y, pA.y);
            float o2 = gru_out(acc[0][2] + bir.x, acc[1][2] + biz.x, acc[2][2] + bin.x,
                               acc[3][2] + bhr.x, acc[4][2] + bhz.x, acc[5][2] + bhn.x, pB.x);
            float o3 = gru_out(acc[0][3] + bir.y, acc[1][3] + biz.y, acc[2][3] + bin.y,
                               acc[3][3] + bhr.y, acc[4][3] + bhz.y, acc[5][3] + bhn.y, pB.y);
            if (rowA < NN) *(float2*)(cur + ((size_t)r * NN + rowA) * 64 + c0) = make_float2(o0, o1);
            if (rowB < NN) *(float2*)(cur + ((size_t)r * NN + rowB) * 64 + c0) = make_float2(o2, o3);
            unsigned chA, clA, chB, clB;
            split2h(o0, o1, chA, clA);
            split2h(o2, o3, chB, clB);
            int wj = j * 4 + t;
            st[g * STROW + wj] = chA;
            st[(g + 8) * STROW + wj] = chB;
            st[TILE_W + g * STROW + wj] = clA;
            st[TILE_W + (g + 8) * STROW + wj] = clB;
        }
    }
    __syncwarp();

    // ===== phase C: attention score; C from stage (2-way accumulator ILP) =====
    {
        unsigned Ch[16], Cl[16];
#pragma unroll
        for (int ks = 0; ks < 4; ks++) {
            int w0 = ks * 8 + t;
            Ch[ks * 4 + 0] = st[g * STROW + w0];
            Ch[ks * 4 + 1] = st[(g + 8) * STROW + w0];
            Ch[ks * 4 + 2] = st[g * STROW + w0 + 4];
            Ch[ks * 4 + 3] = st[(g + 8) * STROW + w0 + 4];
            Cl[ks * 4 + 0] = st[TILE_W + g * STROW + w0];
            Cl[ks * 4 + 1] = st[TILE_W + (g + 8) * STROW + w0];
            Cl[ks * 4 + 2] = st[TILE_W + g * STROW + w0 + 4];
            Cl[ks * 4 + 3] = st[TILE_W + (g + 8) * STROW + w0 + 4];
        }
        float ssum = 0.f;
#pragma unroll
        for (int j = 0; j < 8; j++) {
            float accA[4] = {}, accB[4] = {};
#pragma unroll
            for (int ks = 0; ks < 4; ks++) {
                uint2 F = __ldg(g_wfrag + WB + WF_ATT + (((j * 4 + ks) << 5) + lane));
                mma2((ks & 1) ? accB : accA, Ch + ks * 4, Cl + ks * 4, F);
            }
            int c0 = j * 8 + 2 * t;
            float2 kbv = *(const float2*)(kb + c0);
            float2 qv  = *(const float2*)(q + c0);
            if (rowA < NN)
                ssum += qv.x * tanhf(accA[0] + accB[0] + kbv.x)
                      + qv.y * tanhf(accA[1] + accB[1] + kbv.y);
            if (rowB < NN)
                ssum += qv.x * tanhf(accA[2] + accB[2] + kbv.x)
                      + qv.y * tanhf(accA[3] + accB[3] + kbv.y);
        }
#pragma unroll
        for (int o = 16; o; o >>= 1) ssum += __shfl_down_sync(0xffffffffu, ssum, o);
        if (lane == 0) atomicAdd(&g_score[layer * 3 + r], ssum);
    }
}

// ---------------- softmax helper (inline, per thread) ----------------
__device__ __forceinline__ void softmax3(int layer, float& a0, float& a1, float& a2) {
    const float inv = 1.0f / (float)NN;
    float s0 = g_score[layer * 3 + 0] * inv;
    float s1 = g_score[layer * 3 + 1] * inv;
    float s2 = g_score[layer * 3 + 2] * inv;
    float m = fmaxf(s0, fmaxf(s1, s2));
    float e0 = __expf(s0 - m), e1 = __expf(s1 - m), e2 = __expf(s2 - m);
    float d = 1.f / (e0 + e1 + e2);
    a0 = e0 * d; a1 = e1 * d; a2 = e2 * d;
}

// ---------------- attention mix (softmax fused): fp32 + fp16 outputs ----------------
__global__ void k_mix(const float* __restrict__ cur) {
    int i = blockIdx.x * blockDim.x + threadIdx.x;
    if (i >= NN * 16) return;
    float a0, a1, a2;
    softmax3(0, a0, a1, a2);
    const float4* c = (const float4*)cur;
    float4 v0 = c[i], v1 = c[i + (size_t)NN * 16], v2 = c[i + (size_t)2 * NN * 16];
    float4 o;
    o.x = a0 * v0.x + a1 * v1.x + a2 * v2.x;
    o.y = a0 * v0.y + a1 * v1.y + a2 * v2.y;
    o.z = a0 * v0.z + a1 * v1.z + a2 * v2.z;
    o.w = a0 * v0.w + a1 * v1.w + a2 * v2.w;
    ((float4*)g_mix)[i] = o;
    uint2 h;
    h.x = pack_h2(o.x, o.y);
    h.y = pack_h2(o.z, o.w);
    *(uint2*)(g_mixh + (size_t)i * 2) = h;
}

// ---------------- final projection (softmax fused) ----------------
__global__ __launch_bounds__(128) void k_zfuse(
    const float* __restrict__ cur2, const float* __restrict__ postW,
    const float* __restrict__ postb) {
    int node = blockIdx.x * blockDim.x + threadIdx.x;
    if (node >= NN) return;
    float a0, a1, a2;
    softmax3(1, a0, a1, a2);
    const float4* c0 = (const float4*)(cur2 + (size_t)node * 64);
    const float4* c1 = (const float4*)(cur2 + ((size_t)NN + node) * 64);
    const float4* c2 = (const float4*)(cur2 + ((size_t)2 * NN + node) * 64);
    const float4* w0 = (const float4*)postW;
    const float4* w1 = (const float4*)(postW + 64);
    float z0 = postb[0], z1 = postb[1];
#pragma unroll
    for (int i = 0; i < 16; i++) {
        float4 u0 = c0[i], u1 = c1[i], u2 = c2[i];
        float4 m;
        m.x = a0 * u0.x + a1 * u1.x + a2 * u2.x;
        m.y = a0 * u0.y + a1 * u1.y + a2 * u2.y;
        m.z = a0 * u0.z + a1 * u1.z + a2 * u2.z;
        m.w = a0 * u0.w + a1 * u1.w + a2 * u2.w;
        float4 p0 = w0[i], p1 = w1[i];
        z0 += m.x * p0.x + m.y * p0.y + m.z * p0.z + m.w * p0.w;
        z1 += m.x * p1.x + m.y * p1.y + m.z * p1.z + m.w * p1.w;
    }
    g_z[2 * node] = z0;
    g_z[2 * node + 1] = z1;
}

// ---------------- link scores ----------------
__global__ void k_score(const int* __restrict__ eli, const float* __restrict__ rel,
                        float* __restrict__ scores) {
    int idx = blockIdx.x * blockDim.x + threadIdx.x;
    if (idx >= RR * LL) return;
    int r = idx / LL;
    int l = idx - r * LL;
    int hd = eli[(size_t)r * 2 * LL + l];
    int tl = eli[(size_t)r * 2 * LL + LL + l];
    float hr = g_z[2 * hd], hi = g_z[2 * hd + 1];
    float tr = g_z[2 * tl], ti = g_z[2 * tl + 1];
    float rr = rel[2 * r], ri = rel[2 * r + 1];
    scores[idx] = hr * rr * tr + hi * rr * ti + hr * ri * ti - hi * ri * tr;
}

// ---------------- host ----------------
extern "C" void kernel_launch(void* const* d_in, const int* in_sizes, int n_in,
                              void* d_out, int out_size) {
    const float* x      = (const float*)d_in[0];
    const int*   ei     = (const int*)d_in[1];
    const int*   eli    = (const int*)d_in[2];
    const float* past1  = (const float*)d_in[3];
    const float* past2  = (const float*)d_in[4];
    const float* W1rel  = (const float*)d_in[5];
    const float* b1rel  = (const float*)d_in[6];
    const float* W1root = (const float*)d_in[7];
    const float* g1Wi   = (const float*)d_in[8];
    const float* g1Wh   = (const float*)d_in[9];
    const float* g1bi   = (const float*)d_in[10];
    const float* g1bh   = (const float*)d_in[11];
    const float* k1W    = (const float*)d_in[12];
    const float* k1b    = (const float*)d_in[13];
    const float* q1     = (const float*)d_in[14];
    const float* W2rel  = (const float*)d_in[15];
    const float* b2rel  = (const float*)d_in[16];
    const float* W2root = (const float*)d_in[17];
    const float* g2Wi   = (const float*)d_in[18];
    const float* g2Wh   = (const float*)d_in[19];
    const float* g2bi   = (const float*)d_in[20];
    const float* g2bh   = (const float*)d_in[21];
    const float* k2W    = (const float*)d_in[22];
    const float* k2b    = (const float*)d_in[23];
    const float* q2     = (const float*)d_in[24];
    const float* postW  = (const float*)d_in[25];
    const float* postb  = (const float*)d_in[26];
    const float* relemb = (const float*)d_in[27];

    float* out    = (float*)d_out;
    float* scores = out;
    float* cur1   = out + (size_t)RR * LL;
    float* cur2   = cur1 + (size_t)RR * NN * 64;

    dim3 gridL((NN + 127) / 128, RR);   // 782 x 3
    const int scat_blocks = (RR * EE * 8 + 255) / 256;

    k_zeroall<<<(2 * RR * NN * 8 + 255) / 256, 256>>>(x);
    k_presplit<<<(2 * WF_LAYER + 255) / 256, 256>>>(
        W1rel, W1root, g1Wi, g1Wh, k1W, W2rel, W2root, g2Wi, g2Wh, k2W);
    k_scatter<<<scat_blocks, 256>>>(0, ei);
    k_layer<<<gridL, 256>>>(x, 0, past1, b1rel, g1bi, g1bh, k1b, q1, cur1);
    k_mix<<<(NN * 16 + 255) / 256, 256>>>(cur1);
    k_scatter<<<scat_blocks, 256>>>(1, ei);   // profiled launch (-s 5 -c 1)
    k_layer<<<gridL, 256>>>(x, 1, past2, b2rel, g2bi, g2bh, k2b, q2, cur2);
    k_zfuse<<<(NN + 127) / 128, 128>>>(cur2, postW, postb);
    k_score<<<(RR * LL + 255) / 256, 256>>>(eli, relemb, scores);
}

// round 12
// speedup vs baseline: 2.0988x; 1.3458x over previous
#include <cuda_runtime.h>
#include <cstdint>

#define NN 100000
#define RR 3
#define EE 800000
#define LL 200000

// ---------------- scratch ----------------
// fp16 tables: 32 f16x2 words per node row
__device__ __align__(16) unsigned g_agg_h[(size_t)2 * RR * NN * 32];
__device__ __align__(16) unsigned g_xh[(size_t)NN * 32];    // x in fp16
__device__ __align__(16) unsigned g_mixh[(size_t)NN * 32];  // mix in fp16
__device__ __align__(16) float g_z[(size_t)NN * 2];
__device__ float g_score[6];   // [layer*3 + r]

// fp16 weight fragments, MMA B-fragment order (uint2 = 8 B per lane-frag)
#define WF_REL  0
#define WF_ROOT 3072
#define WF_WI   6144
#define WF_WH   9216
#define WF_ATT  12288
#define WF_LAYER 13312
__device__ __align__(16) uint2 g_wfrag[2 * WF_LAYER];

// SMEM weight slice offsets (uint2 units): rel, root (r-slices), wi, wh, att
#define SREL  0
#define SROOT 1024
#define SWI   2048
#define SWH   5120
#define SATT  8192
#define SW_U2 9216                 // 73728 bytes
#define STROW 36
#define WSTW  576                  // stage words per warp (16 rows x 36)
#define SM_TOTAL (SW_U2 * 8 + 8 * WSTW * 4)   // 73728 + 18432 = 92160 B

// ---------------- fp16 helpers ----------------
__device__ __forceinline__ unsigned pack_h2(float x, float y) {   // lo=x, hi=y
    unsigned d;
    asm("cvt.rn.f16x2.f32 %0, %1, %2;" : "=r"(d) : "f"(y), "f"(x));
    return d;
}
__device__ __forceinline__ void mma_h(float* d, const unsigned* a, unsigned b0, unsigned b1) {
    asm volatile(
        "mma.sync.aligned.m16n8k16.row.col.f32.f16.f16.f32 "
        "{%0,%1,%2,%3},{%4,%5,%6,%7},{%8,%9},{%0,%1,%2,%3};"
        : "+f"(d[0]), "+f"(d[1]), "+f"(d[2]), "+f"(d[3])
        : "r"(a[0]), "r"(a[1]), "r"(a[2]), "r"(a[3]), "r"(b0), "r"(b1));
}
// load one fragment (4 words) from a packed fp16 table row pair
__device__ __forceinline__ void load_frag16(const unsigned* tbl, int nA, int nB, int ks, int t,
                                            unsigned* f) {
    int w0 = ks * 8 + t;
    f[0] = tbl[(size_t)nA * 32 + w0];
    f[1] = tbl[(size_t)nB * 32 + w0];
    f[2] = tbl[(size_t)nA * 32 + w0 + 4];
    f[3] = tbl[(size_t)nB * 32 + w0 + 4];
}
// load + convert one fragment from fp32 [*, 64] matrix (single fp16, no residual)
__device__ __forceinline__ void load_frag32(const float* base, int nA, int nB, int k0,
                                            unsigned* f) {
    float2 v;
    v = *(const float2*)(base + (size_t)nA * 64 + k0);      f[0] = pack_h2(v.x, v.y);
    v = *(const float2*)(base + (size_t)nB * 64 + k0);      f[1] = pack_h2(v.x, v.y);
    v = *(const float2*)(base + (size_t)nA * 64 + k0 + 8);  f[2] = pack_h2(v.x, v.y);
    v = *(const float2*)(base + (size_t)nB * 64 + k0 + 8);  f[3] = pack_h2(v.x, v.y);
}

// ---------------- presplit ALL weights (both layers) to fp16 fragments ----------------
__global__ void k_presplit(
    const float* __restrict__ w1rel, const float* __restrict__ w1root,
    const float* __restrict__ wi1, const float* __restrict__ wh1,
    const float* __restrict__ kw1,
    const float* __restrict__ w2rel, const float* __restrict__ w2root,
    const float* __restrict__ wi2, const float* __restrict__ wh2,
    const float* __restrict__ kw2) {
    int f = blockIdx.x * blockDim.x + threadIdx.x;
    if (f >= 2 * WF_LAYER) return;
    int l = f / WF_LAYER;
    int fo = f - l * WF_LAYER;
    const float* W;
    int fl;
    if (fo < 3072)       { W = l ? w2rel : w1rel;   fl = fo; }
    else if (fo < 6144)  { W = l ? w2root : w1root; fl = fo - 3072; }
    else if (fo < 9216)  { W = l ? wi2 : wi1;       fl = fo - 6144; }
    else if (fo < 12288) { W = l ? wh2 : wh1;       fl = fo - 9216; }
    else                 { W = l ? kw2 : kw1;       fl = fo - 12288; }
    int lane = fl & 31;
    int ks = (fl >> 5) & 3;
    int j = fl >> 7;
    int g = lane >> 2, t = lane & 3;
    const float* row = W + (size_t)(j * 8 + g) * 64;
    int k0 = ks * 16 + 2 * t;
    g_wfrag[f] = make_uint2(pack_h2(row[k0], row[k0 + 1]),
                            pack_h2(row[k0 + 8], row[k0 + 9]));
}

// ---------------- zero agg (fp16) + convert x -> fp16 + zero scores ----------------
__global__ void k_zeroall(const float* __restrict__ x) {
    int i = blockIdx.x * blockDim.x + threadIdx.x;
    const int totz = 2 * RR * NN * 8;   // uint4 count of g_agg_h
    if (i < totz) ((uint4*)g_agg_h)[i] = make_uint4(0u, 0u, 0u, 0u);
    if (i < NN * 8) {
        const float4* p = (const float4*)(x + (size_t)i * 8);
        float4 v0 = p[0], v1 = p[1];
        ((uint4*)g_xh)[i] = make_uint4(pack_h2(v0.x, v0.y), pack_h2(v0.z, v0.w),
                                       pack_h2(v1.x, v1.y), pack_h2(v1.z, v1.w));
    }
    if (i < 6) g_score[i] = 0.f;
}

// ---------------- scatter: agg[layer][r][dst] += feat16[src], red.v4.f16x2 ----------------
__global__ void k_scatter(int layer, const int* __restrict__ ei) {
    unsigned idx = blockIdx.x * blockDim.x + threadIdx.x;
    if (idx >= (unsigned)RR * EE * 8u) return;
    const unsigned* src = layer ? g_mixh : g_xh;
    unsigned chunk = idx & 7u;
    unsigned e = idx >> 3;
    unsigned r = e / EE;
    unsigned eo = e - r * EE;
    int s = ei[(size_t)r * 2 * EE + eo];
    int d = ei[(size_t)r * 2 * EE + EE + eo];
    uint4 v = *(const uint4*)(src + (size_t)s * 32 + chunk * 4);
    unsigned* o = g_agg_h + ((size_t)((size_t)layer * RR + r) * NN + d) * 32 + chunk * 4;
    asm volatile("red.global.add.noftz.v4.f16x2 [%0], {%1, %2, %3, %4};"
                 :: "l"(o), "r"(v.x), "r"(v.y), "r"(v.z), "r"(v.w) : "memory");
}

// ---------------- GRU epilogue ----------------
__device__ __forceinline__ float gru_out(float gi_r, float gi_z, float gi_n,
                                         float gh_r, float gh_z, float gh_n, float p) {
    float rg = 1.f / (1.f + __expf(-(gi_r + gh_r)));
    float zg = 1.f / (1.f + __expf(-(gi_z + gh_z)));
    float ng = tanhf(gi_n + rg * gh_n);
    return (1.f - zg) * ng + zg * p;
}

// ---------------- fused layer: conv -> GRU -> attention score ----------------
__global__ __launch_bounds__(256, 2) void k_layer(
    int layer,
    const float* __restrict__ past,
    const float* __restrict__ brel,
    const float* __restrict__ bi, const float* __restrict__ bh,
    const float* __restrict__ kb, const float* __restrict__ q,
    float* __restrict__ cur) {
    extern __shared__ char smem[];
    uint2* sW = (uint2*)smem;                                  // 9216 uint2 weight slices
    unsigned* stage = (unsigned*)(smem + SW_U2 * 8);           // 8 x 576 words
    const int r = blockIdx.y, tid = threadIdx.x;
    const int lane = tid & 31, warp = tid >> 5;
    const int g = lane >> 2, t = lane & 3;
    const int rowA = blockIdx.x * 128 + warp * 16 + g;
    const int rowB = rowA + 8;
    const int nA = min(rowA, NN - 1), nB = min(rowB, NN - 1);
    const unsigned* Ab16 = g_agg_h + (size_t)((size_t)layer * RR + r) * NN * 32;
    const unsigned* Rb16 = layer ? g_mixh : g_xh;
    const float* Pbase = past + (size_t)r * NN * 64;
    unsigned* st = stage + warp * WSTW;

    // ---- cooperative copy of this r's weight fragments into SMEM ----
    {
        const uint2* wb = g_wfrag + layer * WF_LAYER;
        uint4* sW4 = (uint4*)sW;
        for (int i = tid; i < 4608; i += 256) {
            const uint4* s;
            if (i < 512)       s = (const uint4*)(wb + WF_REL + r * 1024) + i;
            else if (i < 1024) s = (const uint4*)(wb + WF_ROOT + r * 1024) + (i - 512);
            else if (i < 2560) s = (const uint4*)(wb + WF_WI) + (i - 1024);
            else if (i < 4096) s = (const uint4*)(wb + WF_WH) + (i - 2560);
            else               s = (const uint4*)(wb + WF_ATT) + (i - 4096);
            sW4[i] = *s;
        }
    }
    __syncthreads();

    // ===== phase A: graphconv -> H (fp16) into stage =====
    {
        unsigned Ah[16], Rh[16];
#pragma unroll
        for (int ks = 0; ks < 4; ks++) {
            load_frag16(Ab16, nA, nB, ks, t, Ah + ks * 4);
            load_frag16(Rb16, nA, nB, ks, t, Rh + ks * 4);
        }
#pragma unroll
        for (int j = 0; j < 8; j++) {
            float acc0[4] = {}, acc1[4] = {};
#pragma unroll
            for (int ks = 0; ks < 4; ks++) {
                uint2 Fr = sW[SREL + ((j * 4 + ks) << 5) + lane];
                uint2 Fo = sW[SROOT + ((j * 4 + ks) << 5) + lane];
                mma_h(acc0, Ah + ks * 4, Fr.x, Fr.y);
                mma_h(acc1, Rh + ks * 4, Fo.x, Fo.y);
            }
            int c0 = j * 8 + 2 * t;
            float2 bb = *(const float2*)(brel + r * 64 + c0);
            int wj = j * 4 + t;
            st[g * STROW + wj] = pack_h2(fmaxf(acc0[0] + acc1[0] + bb.x, 0.f),
                                         fmaxf(acc0[1] + acc1[1] + bb.y, 0.f));
            st[(g + 8) * STROW + wj] = pack_h2(fmaxf(acc0[2] + acc1[2] + bb.x, 0.f),
                                               fmaxf(acc0[3] + acc1[3] + bb.y, 0.f));
        }
    }
    __syncwarp();

    // ===== phase B: GRU; H from stage, past from global; C -> stage =====
    {
        unsigned Hh[16], Ph[16];
#pragma unroll
        for (int ks = 0; ks < 4; ks++) {
            int w0 = ks * 8 + t;
            Hh[ks * 4 + 0] = st[g * STROW + w0];
            Hh[ks * 4 + 1] = st[(g + 8) * STROW + w0];
            Hh[ks * 4 + 2] = st[g * STROW + w0 + 4];
            Hh[ks * 4 + 3] = st[(g + 8) * STROW + w0 + 4];
            load_frag32(Pbase, nA, nB, ks * 16 + 2 * t, Ph + ks * 4);
        }
        __syncwarp();
#pragma unroll
        for (int j = 0; j < 8; j++) {
            float acc[6][4] = {};
#pragma unroll
            for (int ks = 0; ks < 4; ks++) {
#pragma unroll
                for (int m = 0; m < 3; m++) {
                    uint2 Fi = sW[SWI + (((m * 8 + j) * 4 + ks) << 5) + lane];
                    uint2 Fh = sW[SWH + (((m * 8 + j) * 4 + ks) << 5) + lane];
                    mma_h(acc[m],     Hh + ks * 4, Fi.x, Fi.y);
                    mma_h(acc[3 + m], Ph + ks * 4, Fh.x, Fh.y);
                }
            }
            int c0 = j * 8 + 2 * t;
            float2 bir = *(const float2*)(bi + c0);
            float2 biz = *(const float2*)(bi + 64 + c0);
            float2 bin = *(const float2*)(bi + 128 + c0);
            float2 bhr = *(const float2*)(bh + c0);
            float2 bhz = *(const float2*)(bh + 64 + c0);
            float2 bhn = *(const float2*)(bh + 128 + c0);
            float2 pA = *(const float2*)(Pbase + (size_t)nA * 64 + c0);
            float2 pB = *(const float2*)(Pbase + (size_t)nB * 64 + c0);
            float o0 = gru_out(acc[0][0] + bir.x, acc[1][0] + biz.x, acc[2][0] + bin.x,
                               acc[3][0] + bhr.x, acc[4][0] + bhz.x, acc[5][0] + bhn.x, pA.x);
            float o1 = gru_out(acc[0][1] + bir.y, acc[1][1] + biz.y, acc[2][1] + bin.y,
                               acc[3][1] + bhr.y, acc[4][1] + bhz.y, acc[5][1] + bhn.y, pA.y);
            float o2 = gru_out(acc[0][2] + bir.x, acc[1][2] + biz.x, acc[2][2] + bin.x,
                               acc[3][2] + bhr.x, acc[4][2] + bhz.x, acc[5][2] + bhn.x, pB.x);
            float o3 = gru_out(acc[0][3] + bir.y, acc[1][3] + biz.y, acc[2][3] + bin.y,
                               acc[3][3] + bhr.y, acc[4][3] + bhz.y, acc[5][3] + bhn.y, pB.y);
            if (rowA < NN) *(float2*)(cur + ((size_t)r * NN + rowA) * 64 + c0) = make_float2(o0, o1);
            if (rowB < NN) *(float2*)(cur + ((size_t)r * NN + rowB) * 64 + c0) = make_float2(o2, o3);
            int wj = j * 4 + t;
            st[g * STROW + wj] = pack_h2(o0, o1);
            st[(g + 8) * STROW + wj] = pack_h2(o2, o3);
        }
    }
    __syncwarp();

    // ===== phase C: attention score; C from stage (2-way accumulator ILP) =====
    {
        unsigned Ch[16];
#pragma unroll
        for (int ks = 0; ks < 4; ks++) {
            int w0 = ks * 8 + t;
            Ch[ks * 4 + 0] = st[g * STROW + w0];
            Ch[ks * 4 + 1] = st[(g + 8) * STROW + w0];
            Ch[ks * 4 + 2] = st[g * STROW + w0 + 4];
            Ch[ks * 4 + 3] = st[(g + 8) * STROW + w0 + 4];
        }
        float ssum = 0.f;
#pragma unroll
        for (int j = 0; j < 8; j++) {
            float accA[4] = {}, accB[4] = {};
#pragma unroll
            for (int ks = 0; ks < 4; ks++) {
                uint2 F = sW[SATT + ((j * 4 + ks) << 5) + lane];
                mma_h((ks & 1) ? accB : accA, Ch + ks * 4, F.x, F.y);
            }
            int c0 = j * 8 + 2 * t;
            float2 kbv = *(const float2*)(kb + c0);
            float2 qv  = *(const float2*)(q + c0);
            if (rowA < NN)
                ssum += qv.x * tanhf(accA[0] + accB[0] + kbv.x)
                      + qv.y * tanhf(accA[1] + accB[1] + kbv.y);
            if (rowB < NN)
                ssum += qv.x * tanhf(accA[2] + accB[2] + kbv.x)
                      + qv.y * tanhf(accA[3] + accB[3] + kbv.y);
        }
#pragma unroll
        for (int o = 16; o; o >>= 1) ssum += __shfl_down_sync(0xffffffffu, ssum, o);
        if (lane == 0) atomicAdd(&g_score[layer * 3 + r], ssum);
    }
}

// ---------------- softmax helper (inline, per thread) ----------------
__device__ __forceinline__ void softmax3(int layer, float& a0, float& a1, float& a2) {
    const float inv = 1.0f / (float)NN;
    float s0 = g_score[layer * 3 + 0] * inv;
    float s1 = g_score[layer * 3 + 1] * inv;
    float s2 = g_score[layer * 3 + 2] * inv;
    float m = fmaxf(s0, fmaxf(s1, s2));
    float e0 = __expf(s0 - m), e1 = __expf(s1 - m), e2 = __expf(s2 - m);
    float d = 1.f / (e0 + e1 + e2);
    a0 = e0 * d; a1 = e1 * d; a2 = e2 * d;
}

// ---------------- attention mix (softmax fused): fp16 output only ----------------
__global__ void k_mix(const float* __restrict__ cur) {
    int i = blockIdx.x * blockDim.x + threadIdx.x;
    if (i >= NN * 16) return;
    float a0, a1, a2;
    softmax3(0, a0, a1, a2);
    const float4* c = (const float4*)cur;
    float4 v0 = c[i], v1 = c[i + (size_t)NN * 16], v2 = c[i + (size_t)2 * NN * 16];
    float ox = a0 * v0.x + a1 * v1.x + a2 * v2.x;
    float oy = a0 * v0.y + a1 * v1.y + a2 * v2.y;
    float oz = a0 * v0.z + a1 * v1.z + a2 * v2.z;
    float ow = a0 * v0.w + a1 * v1.w + a2 * v2.w;
    *(uint2*)(g_mixh + (size_t)i * 2) = make_uint2(pack_h2(ox, oy), pack_h2(oz, ow));
}

// ---------------- final projection (softmax fused) ----------------
__global__ __launch_bounds__(128) void k_zfuse(
    const float* __restrict__ cur2, const float* __restrict__ postW,
    const float* __restrict__ postb) {
    int node = blockIdx.x * blockDim.x + threadIdx.x;
    if (node >= NN) return;
    float a0, a1, a2;
    softmax3(1, a0, a1, a2);
    const float4* c0 = (const float4*)(cur2 + (size_t)node * 64);
    const float4* c1 = (const float4*)(cur2 + ((size_t)NN + node) * 64);
    const float4* c2 = (const float4*)(cur2 + ((size_t)2 * NN + node) * 64);
    const float4* w0 = (const float4*)postW;
    const float4* w1 = (const float4*)(postW + 64);
    float z0 = postb[0], z1 = postb[1];
#pragma unroll
    for (int i = 0; i < 16; i++) {
        float4 u0 = c0[i], u1 = c1[i], u2 = c2[i];
        float4 m;
        m.x = a0 * u0.x + a1 * u1.x + a2 * u2.x;
        m.y = a0 * u0.y + a1 * u1.y + a2 * u2.y;
        m.z = a0 * u0.z + a1 * u1.z + a2 * u2.z;
        m.w = a0 * u0.w + a1 * u1.w + a2 * u2.w;
        float4 p0 = w0[i], p1 = w1[i];
        z0 += m.x * p0.x + m.y * p0.y + m.z * p0.z + m.w * p0.w;
        z1 += m.x * p1.x + m.y * p1.y + m.z * p1.z + m.w * p1.w;
    }
    g_z[2 * node] = z0;
    g_z[2 * node + 1] = z1;
}

// ---------------- link scores ----------------
__global__ void k_score(const int* __restrict__ eli, const float* __restrict__ rel,
                        float* __restrict__ scores) {
    int idx = blockIdx.x * blockDim.x + threadIdx.x;
    if (idx >= RR * LL) return;
    int r = idx / LL;
    int l = idx - r * LL;
    int hd = eli[(size_t)r * 2 * LL + l];
    int tl = eli[(size_t)r * 2 * LL + LL + l];
    float hr = g_z[2 * hd], hi = g_z[2 * hd + 1];
    float tr = g_z[2 * tl], ti = g_z[2 * tl + 1];
    float rr = rel[2 * r], ri = rel[2 * r + 1];
    scores[idx] = hr * rr * tr + hi * rr * ti + hr * ri * ti - hi * ri * tr;
}

// ---------------- host ----------------
extern "C" void kernel_launch(void* const* d_in, const int* in_sizes, int n_in,
                              void* d_out, int out_size) {
    const float* x      = (const float*)d_in[0];
    const int*   ei     = (const int*)d_in[1];
    const int*   eli    = (const int*)d_in[2];
    const float* past1  = (const float*)d_in[3];
    const float* past2  = (const float*)d_in[4];
    const float* W1rel  = (const float*)d_in[5];
    const float* b1rel  = (const float*)d_in[6];
    const float* W1root = (const float*)d_in[7];
    const float* g1Wi   = (const float*)d_in[8];
    const float* g1Wh   = (const float*)d_in[9];
    const float* g1bi   = (const float*)d_in[10];
    const float* g1bh   = (const float*)d_in[11];
    const float* k1W    = (const float*)d_in[12];
    const float* k1b    = (const float*)d_in[13];
    const float* q1     = (const float*)d_in[14];
    const float* W2rel  = (const float*)d_in[15];
    const float* b2rel  = (const float*)d_in[16];
    const float* W2root = (const float*)d_in[17];
    const float* g2Wi   = (const float*)d_in[18];
    const float* g2Wh   = (const float*)d_in[19];
    const float* g2bi   = (const float*)d_in[20];
    const float* g2bh   = (const float*)d_in[21];
    const float* k2W    = (const float*)d_in[22];
    const float* k2b    = (const float*)d_in[23];
    const float* q2     = (const float*)d_in[24];
    const float* postW  = (const float*)d_in[25];
    const float* postb  = (const float*)d_in[26];
    const float* relemb = (const float*)d_in[27];

    float* out    = (float*)d_out;
    float* scores = out;
    float* cur1   = out + (size_t)RR * LL;
    float* cur2   = cur1 + (size_t)RR * NN * 64;

    cudaFuncSetAttribute(k_layer, cudaFuncAttributeMaxDynamicSharedMemorySize, SM_TOTAL);

    dim3 gridL((NN + 127) / 128, RR);   // 782 x 3
    const int scat_blocks = (RR * EE * 8 + 255) / 256;

    k_zeroall<<<(2 * RR * NN * 8 + 255) / 256, 256>>>(x);
    k_presplit<<<(2 * WF_LAYER + 255) / 256, 256>>>(
        W1rel, W1root, g1Wi, g1Wh, k1W, W2rel, W2root, g2Wi, g2Wh, k2W);
    k_scatter<<<scat_blocks, 256>>>(0, ei);
    k_layer<<<gridL, 256, SM_TOTAL>>>(0, past1, b1rel, g1bi, g1bh, k1b, q1, cur1);
    k_mix<<<(NN * 16 + 255) / 256, 256>>>(cur1);
    k_scatter<<<scat_blocks, 256>>>(1, ei);   // profiled launch (-s 5 -c 1)
    k_layer<<<gridL, 256, SM_TOTAL>>>(1, past2, b2rel, g2bi, g2bh, k2b, q2, cur2);
    k_zfuse<<<(NN + 127) / 128, 128>>>(cur2, postW, postb);
    k_score<<<(RR * LL + 255) / 256, 256>>>(eli, relemb, scores);
}